// round 2
// baseline (speedup 1.0000x reference)
#include <cuda_runtime.h>

#define Nn 50000
#define Ee 1200000
#define Hh 64
#define Ll 2

// ---------------- scratch (device globals; no allocation allowed) ----------------
__device__ float g_deg[Nn];          // degree, then dinv in-place
__device__ int   g_cnt[Nn];          // histogram / scatter cursors
__device__ int   g_rowstart[Nn + 1]; // CSR row offsets
__device__ int   g_colS[Ee];         // CSR sorted col indices
__device__ float g_nwS[Ee];          // CSR sorted normalized weights
__device__ float g_tx1[Nn * Hh];     // Chebyshev T1
__device__ float g_tx2[Nn * Hh];     // Chebyshev T2
__device__ float g_Wbig[Ll * 256 * 256]; // rearranged weights [l][kin][o*4+g]
__device__ float g_bias[Ll * 256];       // b_cheb + b_gate, interleaved

// ---------------- small helpers ----------------
__device__ __forceinline__ unsigned long long pk2(float x) {
    unsigned long long r;
    asm("mov.b64 %0, {%1, %1};" : "=l"(r) : "f"(x));
    return r;
}
__device__ __forceinline__ void fma2(unsigned long long& d, unsigned long long a, unsigned long long b) {
    asm("fma.rn.f32x2 %0, %1, %2, %0;" : "+l"(d) : "l"(a), "l"(b));
}
__device__ __forceinline__ float2 upk2(unsigned long long v) {
    float2 r;
    asm("mov.b64 {%0, %1}, %2;" : "=f"(r.x), "=f"(r.y) : "l"(v));
    return r;
}
__device__ __forceinline__ float sigf(float x) {
    return __fdividef(1.0f, 1.0f + __expf(-x));
}
__device__ __forceinline__ float tanhfast(float x) {
    return 1.0f - __fdividef(2.0f, 1.0f + __expf(2.0f * x));
}

// ---------------- setup kernels ----------------
__global__ void k_zero() {
    int i = blockIdx.x * blockDim.x + threadIdx.x;
    if (i < Nn) { g_deg[i] = 0.0f; g_cnt[i] = 0; }
}

__global__ void k_hist(const int* __restrict__ row, const float* __restrict__ w) {
    int e = blockIdx.x * blockDim.x + threadIdx.x;
    if (e < Ee) {
        int r = row[e];
        atomicAdd(&g_deg[r], w[e]);
        atomicAdd(&g_cnt[r], 1);
    }
}

__global__ void k_dinv() {
    int i = blockIdx.x * blockDim.x + threadIdx.x;
    if (i < Nn) {
        float d = g_deg[i];
        g_deg[i] = (d > 0.0f) ? rsqrtf(d) : 0.0f;
    }
}

// single-block exclusive scan of g_cnt -> g_rowstart, zeroes g_cnt for scatter
__global__ void k_scan() {
    __shared__ int sm[1024];
    int t = threadIdx.x;
    const int C = (Nn + 1023) / 1024;
    int lo = t * C;
    int hi = lo + C; if (hi > Nn) hi = Nn;
    int s = 0;
    for (int i = lo; i < hi; i++) s += g_cnt[i];
    sm[t] = s;
    __syncthreads();
    for (int d = 1; d < 1024; d <<= 1) {
        int v = (t >= d) ? sm[t - d] : 0;
        __syncthreads();
        sm[t] += v;
        __syncthreads();
    }
    int run = sm[t] - s; // exclusive prefix
    for (int i = lo; i < hi; i++) {
        int v = g_cnt[i];
        g_rowstart[i] = run;
        run += v;
        g_cnt[i] = 0;
    }
    if (t == 1023) g_rowstart[Nn] = Ee;
}

__global__ void k_scatter(const int* __restrict__ row, const int* __restrict__ col,
                          const float* __restrict__ w) {
    int e = blockIdx.x * blockDim.x + threadIdx.x;
    if (e < Ee) {
        int r = row[e], c = col[e];
        int pos = g_rowstart[r] + atomicAdd(&g_cnt[r], 1);
        g_colS[pos] = c;
        g_nwS[pos] = -g_deg[r] * w[e] * g_deg[c];
    }
}

// rearrange weights: W_big[l][kin][o*4+g]; kin = s*64+rr, s=0 -> Wx, s=1..3 -> Wcheb[k=s-1]
__global__ void k_wbig(const float* __restrict__ Wx, const float* __restrict__ Wch,
                       const float* __restrict__ bch, const float* __restrict__ bg) {
    int idx = blockIdx.x * blockDim.x + threadIdx.x;
    if (idx < Ll * 65536) {
        int l = idx >> 16;
        int r = idx & 65535;
        int kin = r >> 8;
        int colp = r & 255;
        int g = colp & 3;
        int o = colp >> 2;
        int s = kin >> 6;
        int rr = kin & 63;
        float v;
        if (s == 0) v = Wx[((l * 4 + g) * 64 + rr) * 64 + o];
        else        v = Wch[(((l * 4 + g) * 3 + (s - 1)) * 64 + rr) * 64 + o];
        g_Wbig[idx] = v;
        if (kin == 0)
            g_bias[l * 256 + colp] = bch[(l * 4 + g) * 64 + o] + bg[(l * 4 + g) * 64 + o];
    }
}

// ---------------- SpMM (CSR, warp per row, atomic-free) ----------------
// tx1 = P @ hl
__global__ void __launch_bounds__(256) k_spmm1(const float* __restrict__ hl) {
    int warp = (blockIdx.x * blockDim.x + threadIdx.x) >> 5;
    int lane = threadIdx.x & 31;
    if (warp >= Nn) return;
    int s = g_rowstart[warp], e = g_rowstart[warp + 1];
    int j2 = lane * 2;
    float ax = 0.f, ay = 0.f, bx = 0.f, by = 0.f;
    int i = s;
    for (; i + 1 < e; i += 2) {
        int c0 = g_colS[i], c1 = g_colS[i + 1];
        float w0 = g_nwS[i], w1 = g_nwS[i + 1];
        float2 v0 = *(const float2*)(hl + c0 * 64 + j2);
        float2 v1 = *(const float2*)(hl + c1 * 64 + j2);
        ax += w0 * v0.x; ay += w0 * v0.y;
        bx += w1 * v1.x; by += w1 * v1.y;
    }
    if (i < e) {
        int c0 = g_colS[i];
        float w0 = g_nwS[i];
        float2 v0 = *(const float2*)(hl + c0 * 64 + j2);
        ax += w0 * v0.x; ay += w0 * v0.y;
    }
    *(float2*)(g_tx1 + warp * 64 + j2) = make_float2(ax + bx, ay + by);
}

// tx2 = 2 * (P @ tx1) - hl
__global__ void __launch_bounds__(256) k_spmm2(const float* __restrict__ hl) {
    int warp = (blockIdx.x * blockDim.x + threadIdx.x) >> 5;
    int lane = threadIdx.x & 31;
    if (warp >= Nn) return;
    int s = g_rowstart[warp], e = g_rowstart[warp + 1];
    int j2 = lane * 2;
    float ax = 0.f, ay = 0.f, bx = 0.f, by = 0.f;
    int i = s;
    for (; i + 1 < e; i += 2) {
        int c0 = g_colS[i], c1 = g_colS[i + 1];
        float w0 = g_nwS[i], w1 = g_nwS[i + 1];
        float2 v0 = *(const float2*)(g_tx1 + c0 * 64 + j2);
        float2 v1 = *(const float2*)(g_tx1 + c1 * 64 + j2);
        ax += w0 * v0.x; ay += w0 * v0.y;
        bx += w1 * v1.x; by += w1 * v1.y;
    }
    if (i < e) {
        int c0 = g_colS[i];
        float w0 = g_nwS[i];
        float2 v0 = *(const float2*)(g_tx1 + c0 * 64 + j2);
        ax += w0 * v0.x; ay += w0 * v0.y;
    }
    float2 sv = *(const float2*)(hl + warp * 64 + j2);
    *(float2*)(g_tx2 + warp * 64 + j2) =
        make_float2(2.0f * (ax + bx) - sv.x, 2.0f * (ay + by) - sv.y);
}

// ---------------- fused gate GEMM + LSTM cell ----------------
// Per block: 64 nodes x 256 outputs (4 gates x 64 h). Input K = 256:
// [inp(64) | T0=hl(64) | T1(64) | T2(64)]. Packed f32x2 accumulation.
__global__ void __launch_bounds__(256, 2) k_gates(
    int l,
    const float* __restrict__ inp, const float* __restrict__ hl,
    const float* __restrict__ cl,  const float* __restrict__ wp,
    float* __restrict__ hout, float* __restrict__ cout)
{
    __shared__ __align__(16) float As[64 * 32];
    __shared__ __align__(16) float Bs[32 * 256];
    const float* __restrict__ Wb = g_Wbig + l * 65536;
    const float* __restrict__ bias = g_bias + l * 256;

    int n0 = blockIdx.x * 64;
    int tid = threadIdx.x;
    int tx = tid & 31;        // output channel (o = tx and tx+32)
    int ty = tid >> 5;        // node group (8 nodes each)

    unsigned long long acc[8][4];
#pragma unroll
    for (int i = 0; i < 8; i++)
#pragma unroll
        for (int j = 0; j < 4; j++) acc[i][j] = 0ull;

    for (int ss = 0; ss < 8; ss++) {
        int s = ss >> 1;
        int kh = (ss & 1) * 32;
        const float* A = (s == 0) ? inp : (s == 1) ? hl : (s == 2) ? g_tx1 : g_tx2;
        // load A tile: 64 nodes x 32 k (row-major, no transpose needed: reads are warp-uniform)
#pragma unroll
        for (int i = 0; i < 2; i++) {
            int q = tid + i * 256;          // 0..511
            int n = q >> 3;
            int kq = (q & 7) * 4;
            float4 v = make_float4(0.f, 0.f, 0.f, 0.f);
            if (n0 + n < Nn) v = *(const float4*)(A + (n0 + n) * 64 + kh + kq);
            *(float4*)(As + n * 32 + kq) = v;
        }
        // load B tile: 32 k x 256 cols (straight contiguous copy)
        const float* Wsrc = Wb + (s * 64 + kh) * 256;
#pragma unroll
        for (int i = 0; i < 8; i++) {
            int q = tid + i * 256;
            *(float4*)(Bs + q * 4) = *(const float4*)(Wsrc + q * 4);
        }
        __syncthreads();
#pragma unroll 4
        for (int k = 0; k < 32; k++) {
            const float* br = Bs + k * 256;
            ulonglong2 B0 = *(const ulonglong2*)(br + tx * 4);
            ulonglong2 B1 = *(const ulonglong2*)(br + 128 + tx * 4);
#pragma unroll
            for (int i = 0; i < 8; i++) {
                unsigned long long pa = pk2(As[(ty * 8 + i) * 32 + k]);
                fma2(acc[i][0], pa, B0.x);
                fma2(acc[i][1], pa, B0.y);
                fma2(acc[i][2], pa, B1.x);
                fma2(acc[i][3], pa, B1.y);
            }
        }
        __syncthreads();
    }

    // epilogue: LSTM cell with peepholes
#pragma unroll
    for (int i = 0; i < 8; i++) {
        int n = n0 + ty * 8 + i;
        if (n >= Nn) break;
#pragma unroll
        for (int j = 0; j < 2; j++) {
            int o = tx + j * 32;
            float2 v01 = upk2(acc[i][2 * j]);     // (gate i, gate f)
            float2 v23 = upk2(acc[i][2 * j + 1]); // (gate c, gate o)
            float cv = cl[n * 64 + o];
            float gi = v01.x + bias[4 * o + 0] + wp[o] * cv;
            float gf = v01.y + bias[4 * o + 1] + wp[64 + o] * cv;
            float gt = v23.x + bias[4 * o + 2];
            float go = v23.y + bias[4 * o + 3];
            float iv = sigf(gi);
            float fv = sigf(gf);
            float tv = tanhfast(gt);
            float ct = fv * cv + iv * tv;
            float ov = sigf(go + wp[128 + o] * ct);
            hout[n * 64 + o] = ov * tanhfast(ct);
            cout[n * 64 + o] = ct;
        }
    }
}

// ---------------- final FC ----------------
__global__ void __launch_bounds__(256) k_fc(const float* __restrict__ h1,
                                            const float* __restrict__ fw,
                                            const float* __restrict__ fb,
                                            float* __restrict__ out) {
    int warp = (blockIdx.x * blockDim.x + threadIdx.x) >> 5;
    int lane = threadIdx.x & 31;
    if (warp >= Nn) return;
    float2 v = *(const float2*)(h1 + warp * 64 + lane * 2);
    float2 w = *(const float2*)(fw + lane * 2);
    float s = v.x * w.x + v.y * w.y;
#pragma unroll
    for (int d = 16; d; d >>= 1) s += __shfl_xor_sync(0xffffffffu, s, d);
    if (lane == 0) out[warp] = s + fb[0];
}

// ---------------- launch ----------------
extern "C" void kernel_launch(void* const* d_in, const int* in_sizes, int n_in,
                              void* d_out, int out_size) {
    const float* x   = (const float*)d_in[0];
    const int*   ei  = (const int*)d_in[1];
    const float* ew  = (const float*)d_in[2];
    const float* h   = (const float*)d_in[3];
    const float* c   = (const float*)d_in[4];
    const float* Wx  = (const float*)d_in[5];
    const float* Wch = (const float*)d_in[6];
    const float* bch = (const float*)d_in[7];
    const float* wp  = (const float*)d_in[8];
    const float* bg  = (const float*)d_in[9];
    const float* fw  = (const float*)d_in[10];
    const float* fb  = (const float*)d_in[11];

    float* out  = (float*)d_out;
    float* hout = out + Nn;                 // h_new stacked (L, N, H)
    float* cout = out + Nn + Ll * Nn * Hh;  // c_new stacked (L, N, H)

    const int* row = ei;
    const int* col = ei + Ee;

    k_zero<<<(Nn + 255) / 256, 256>>>();
    k_hist<<<(Ee + 255) / 256, 256>>>(row, ew);
    k_dinv<<<(Nn + 255) / 256, 256>>>();
    k_scan<<<1, 1024>>>();
    k_scatter<<<(Ee + 255) / 256, 256>>>(row, col, ew);
    k_wbig<<<(Ll * 65536 + 255) / 256, 256>>>(Wx, Wch, bch, bg);

    const int spmmBlocks = (Nn * 32 + 255) / 256;  // warp per row
    const int gemmBlocks = (Nn + 63) / 64;

    for (int l = 0; l < Ll; l++) {
        const float* hl  = h + l * Nn * Hh;
        const float* clp = c + l * Nn * Hh;
        const float* inp = (l == 0) ? x : hout;           // layer 1 input = h_new[0]
        float* ho = hout + l * Nn * Hh;
        float* co = cout + l * Nn * Hh;

        k_spmm1<<<spmmBlocks, 256>>>(hl);
        k_spmm2<<<spmmBlocks, 256>>>(hl);
        k_gates<<<gemmBlocks, 256>>>(l, inp, hl, clp, wp + l * 192, ho, co);
    }

    k_fc<<<spmmBlocks, 256>>>(hout + Nn * Hh, fw, fb, out);
}

// round 3
// speedup vs baseline: 1.6411x; 1.6411x over previous
#include <cuda_runtime.h>

#define Nn 50000
#define Ee 1200000
#define Hh 64
#define Ll 2
#define PBLK 196   // ceil(Nn/256)

// ---------------- scratch (device globals; no allocation allowed) ----------------
__device__ float g_deg[Nn];          // degree, then dinv in-place
__device__ int   g_cnt[Nn];          // histogram / scatter cursors
__device__ int   g_part[PBLK];       // per-block partial sums for scan
__device__ int   g_rowstart[Nn + 1]; // CSR row offsets
__device__ int   g_colS[Ee];         // CSR sorted col indices
__device__ float g_nwS[Ee];          // CSR sorted normalized weights
__device__ float g_tx1[Nn * Hh];     // Chebyshev T1
__device__ float g_tx2[Nn * Hh];     // Chebyshev T2
__device__ unsigned int g_Wbig[Ll * 256 * 256]; // tf32 weights in mma-fragment order
__device__ float g_bias[Ll * 256];              // b_cheb + b_gate, col = o*4+g

// ---------------- small helpers ----------------
__device__ __forceinline__ unsigned int tf32r(float f) {
    unsigned int u;
    asm("cvt.rna.tf32.f32 %0, %1;" : "=r"(u) : "f"(f));
    return u;
}
__device__ __forceinline__ void mma8(float* c, unsigned a0, unsigned a1, unsigned a2,
                                     unsigned a3, unsigned b0, unsigned b1) {
    asm volatile(
        "mma.sync.aligned.m16n8k8.row.col.f32.tf32.tf32.f32 "
        "{%0,%1,%2,%3}, {%4,%5,%6,%7}, {%8,%9}, {%0,%1,%2,%3};"
        : "+f"(c[0]), "+f"(c[1]), "+f"(c[2]), "+f"(c[3])
        : "r"(a0), "r"(a1), "r"(a2), "r"(a3), "r"(b0), "r"(b1));
}
__device__ __forceinline__ float sigf(float x) {
    return __fdividef(1.0f, 1.0f + __expf(-x));
}
__device__ __forceinline__ float tanhfast(float x) {
    return 1.0f - __fdividef(2.0f, 1.0f + __expf(2.0f * x));
}

// ---------------- setup kernels ----------------
__global__ void k_zero() {
    int i = blockIdx.x * blockDim.x + threadIdx.x;
    if (i < Nn) { g_deg[i] = 0.0f; g_cnt[i] = 0; }
}

__global__ void k_hist(const int* __restrict__ row, const float* __restrict__ w) {
    int e = blockIdx.x * blockDim.x + threadIdx.x;
    if (e < Ee) {
        int r = row[e];
        atomicAdd(&g_deg[r], w[e]);
        atomicAdd(&g_cnt[r], 1);
    }
}

__global__ void k_dinv() {
    int i = blockIdx.x * blockDim.x + threadIdx.x;
    if (i < Nn) {
        float d = g_deg[i];
        g_deg[i] = (d > 0.0f) ? rsqrtf(d) : 0.0f;
    }
}

// scan phase 1: per-block (256 counts) sums
__global__ void k_part() {
    int i = blockIdx.x * 256 + threadIdx.x;
    int v = (i < Nn) ? g_cnt[i] : 0;
#pragma unroll
    for (int d = 16; d; d >>= 1) v += __shfl_xor_sync(0xffffffffu, v, d);
    __shared__ int ws[8];
    if ((threadIdx.x & 31) == 0) ws[threadIdx.x >> 5] = v;
    __syncthreads();
    if (threadIdx.x == 0) {
        int s = 0;
#pragma unroll
        for (int w = 0; w < 8; w++) s += ws[w];
        g_part[blockIdx.x] = s;
    }
}

// scan phase 2: exclusive scan of the 196 partials (one small block)
__global__ void k_scanpart() {
    __shared__ int sm[256];
    int t = threadIdx.x;
    int v = (t < PBLK) ? g_part[t] : 0;
    sm[t] = v;
    __syncthreads();
    for (int d = 1; d < 256; d <<= 1) {
        int x = (t >= d) ? sm[t - d] : 0;
        __syncthreads();
        sm[t] += x;
        __syncthreads();
    }
    if (t < PBLK) g_part[t] = sm[t] - v;   // exclusive
}

// scan phase 3: per-block exclusive scan + offset -> rowstart, zero cnt
__global__ void k_csr() {
    int tid = threadIdx.x;
    int i = blockIdx.x * 256 + tid;
    int lane = tid & 31, wid = tid >> 5;
    int v = (i < Nn) ? g_cnt[i] : 0;
    int inc = v;
#pragma unroll
    for (int d = 1; d < 32; d <<= 1) {
        int t = __shfl_up_sync(0xffffffffu, inc, d);
        if (lane >= d) inc += t;
    }
    __shared__ int ws[8];
    if (lane == 31) ws[wid] = inc;
    __syncthreads();
    if (tid == 0) {
        int run = 0;
#pragma unroll
        for (int w = 0; w < 8; w++) { int t = ws[w]; ws[w] = run; run += t; }
    }
    __syncthreads();
    int excl = inc - v + ws[wid] + g_part[blockIdx.x];
    if (i <= Nn) g_rowstart[i] = excl;
    if (i < Nn) g_cnt[i] = 0;
}

__global__ void k_scatter(const int* __restrict__ row, const int* __restrict__ col,
                          const float* __restrict__ w) {
    int e = blockIdx.x * blockDim.x + threadIdx.x;
    if (e < Ee) {
        int r = row[e], c = col[e];
        int pos = g_rowstart[r] + atomicAdd(&g_cnt[r], 1);
        g_colS[pos] = c;
        g_nwS[pos] = -g_deg[r] * w[e] * g_deg[c];
    }
}

// Rearrange weights into tf32 + mma B-fragment order.
// Logical B[l][kin][col], col = o*4+g; kin = s*64+rr (s=0 -> Wx, s=1..3 -> Wcheb[s-1]).
// Packed: [kchunk(8)][ntile(32)][kspair(2)][lane(32)][slot(4)]
__global__ void k_wbig(const float* __restrict__ Wx, const float* __restrict__ Wch,
                       const float* __restrict__ bch, const float* __restrict__ bg) {
    int idx = blockIdx.x * blockDim.x + threadIdx.x;
    if (idx < Ll * 65536) {
        int l = idx >> 16;
        int r = idx & 65535;
        int kin = r >> 8;
        int colp = r & 255;
        int g = colp & 3;
        int o = colp >> 2;
        int s = kin >> 6;
        int rr = kin & 63;
        float v;
        if (s == 0) v = Wx[((l * 4 + g) * 64 + rr) * 64 + o];
        else        v = Wch[(((l * 4 + g) * 3 + (s - 1)) * 64 + rr) * 64 + o];
        // packed fragment address
        int kchunk = kin >> 5;
        int kk = kin & 31;
        int kstep = kk >> 3;
        int kr = kk & 7;
        int kp = kstep >> 1;
        int ksh = kstep & 1;
        int ntile = colp >> 3;
        int nr = colp & 7;
        int lane = nr * 4 + (kr & 3);
        int slot = ksh * 2 + (kr >> 2);
        int off = (((kchunk * 32 + ntile) * 2 + kp) * 32 + lane) * 4 + slot;
        g_Wbig[l * 65536 + off] = tf32r(v);
        if (kin == 0)
            g_bias[l * 256 + colp] = bch[(l * 4 + g) * 64 + o] + bg[(l * 4 + g) * 64 + o];
    }
}

// ---------------- SpMM (CSR, warp per row, atomic-free) ----------------
__global__ void __launch_bounds__(256) k_spmm1(const float* __restrict__ hl) {
    int warp = (blockIdx.x * blockDim.x + threadIdx.x) >> 5;
    int lane = threadIdx.x & 31;
    if (warp >= Nn) return;
    int s = g_rowstart[warp], e = g_rowstart[warp + 1];
    int j2 = lane * 2;
    float ax = 0.f, ay = 0.f, bx = 0.f, by = 0.f;
    int i = s;
    for (; i + 1 < e; i += 2) {
        int c0 = g_colS[i], c1 = g_colS[i + 1];
        float w0 = g_nwS[i], w1 = g_nwS[i + 1];
        float2 v0 = *(const float2*)(hl + c0 * 64 + j2);
        float2 v1 = *(const float2*)(hl + c1 * 64 + j2);
        ax += w0 * v0.x; ay += w0 * v0.y;
        bx += w1 * v1.x; by += w1 * v1.y;
    }
    if (i < e) {
        int c0 = g_colS[i];
        float w0 = g_nwS[i];
        float2 v0 = *(const float2*)(hl + c0 * 64 + j2);
        ax += w0 * v0.x; ay += w0 * v0.y;
    }
    *(float2*)(g_tx1 + warp * 64 + j2) = make_float2(ax + bx, ay + by);
}

__global__ void __launch_bounds__(256) k_spmm2(const float* __restrict__ hl) {
    int warp = (blockIdx.x * blockDim.x + threadIdx.x) >> 5;
    int lane = threadIdx.x & 31;
    if (warp >= Nn) return;
    int s = g_rowstart[warp], e = g_rowstart[warp + 1];
    int j2 = lane * 2;
    float ax = 0.f, ay = 0.f, bx = 0.f, by = 0.f;
    int i = s;
    for (; i + 1 < e; i += 2) {
        int c0 = g_colS[i], c1 = g_colS[i + 1];
        float w0 = g_nwS[i], w1 = g_nwS[i + 1];
        float2 v0 = *(const float2*)(g_tx1 + c0 * 64 + j2);
        float2 v1 = *(const float2*)(g_tx1 + c1 * 64 + j2);
        ax += w0 * v0.x; ay += w0 * v0.y;
        bx += w1 * v1.x; by += w1 * v1.y;
    }
    if (i < e) {
        int c0 = g_colS[i];
        float w0 = g_nwS[i];
        float2 v0 = *(const float2*)(g_tx1 + c0 * 64 + j2);
        ax += w0 * v0.x; ay += w0 * v0.y;
    }
    float2 sv = *(const float2*)(hl + warp * 64 + j2);
    *(float2*)(g_tx2 + warp * 64 + j2) =
        make_float2(2.0f * (ax + bx) - sv.x, 2.0f * (ay + by) - sv.y);
}

// ---------------- fused gate GEMM (tf32 mma) + LSTM cell ----------------
// Block: 512 threads = 16 warps (4m x 4n). 128 nodes x 256 cols, K=256 in 8 chunks of 32.
// Warp tile: 32 nodes x 64 cols = 2 m-tiles x 8 n-tiles of m16n8k8.
__global__ void __launch_bounds__(512, 1) k_gates(
    int l,
    const float* __restrict__ inp, const float* __restrict__ hl,
    const float* __restrict__ cl,  const float* __restrict__ wp,
    float* __restrict__ hout, float* __restrict__ cout)
{
    extern __shared__ unsigned int smem[];
    unsigned int* As = smem;                     // 128 x 32, XOR-swizzled (16 KB)
    uint4* Bs = (uint4*)(smem + 128 * 32);       // 2048 x uint4 (32 KB)

    const float* __restrict__ bias = g_bias + l * 256;
    const unsigned int* __restrict__ Wb = g_Wbig + l * 65536;

    int n0 = blockIdx.x * 128;
    int tid = threadIdx.x;
    int lane = tid & 31;
    int w = tid >> 5;
    int warp_m = w >> 2;   // 0..3
    int warp_n = w & 3;    // 0..3

    float acc[2][8][4];
#pragma unroll
    for (int mt = 0; mt < 2; mt++)
#pragma unroll
        for (int nt = 0; nt < 8; nt++)
#pragma unroll
            for (int j = 0; j < 4; j++) acc[mt][nt][j] = 0.f;

    for (int chunk = 0; chunk < 8; chunk++) {
        int s = chunk >> 1;
        int kh = (chunk & 1) * 32;
        const float* A = (s == 0) ? inp : (s == 1) ? hl : (s == 2) ? g_tx1 : g_tx2;
        // A stage: 128 rows x 32 k, tf32-rounded, XOR swizzle (k ^ ((row&7)<<2))
#pragma unroll
        for (int it = 0; it < 2; it++) {
            int q = tid + it * 512;       // 0..1023
            int rrow = q >> 3;
            int c4 = (q & 7) * 4;
            uint4 wv = make_uint4(0u, 0u, 0u, 0u);
            int n = n0 + rrow;
            if (n < Nn) {
                float4 f = *(const float4*)(A + n * 64 + kh + c4);
                wv.x = tf32r(f.x); wv.y = tf32r(f.y);
                wv.z = tf32r(f.z); wv.w = tf32r(f.w);
            }
            *(uint4*)&As[rrow * 32 + (c4 ^ ((rrow & 7) << 2))] = wv;
        }
        // B stage: straight contiguous copy of the packed chunk (32 KB)
        const unsigned int* Bsrc = Wb + chunk * 8192;
#pragma unroll
        for (int it = 0; it < 4; it++) {
            int q = tid + it * 512;       // 0..2047
            Bs[q] = *(const uint4*)(Bsrc + q * 4);
        }
        __syncthreads();

#pragma unroll
        for (int kp = 0; kp < 2; kp++) {
            uint4 bf[8];
#pragma unroll
            for (int nt = 0; nt < 8; nt++)
                bf[nt] = Bs[((warp_n * 8 + nt) * 2 + kp) * 32 + lane];
#pragma unroll
            for (int mt = 0; mt < 2; mt++) {
                int r = warp_m * 32 + mt * 16 + (lane >> 2);
                int k0 = kp * 16 + (lane & 3);
                int sw = (r & 7) << 2;
                unsigned a0 = As[r * 32 + ((k0) ^ sw)];
                unsigned a1 = As[(r + 8) * 32 + ((k0) ^ sw)];
                unsigned a2 = As[r * 32 + ((k0 + 4) ^ sw)];
                unsigned a3 = As[(r + 8) * 32 + ((k0 + 4) ^ sw)];
                unsigned a4 = As[r * 32 + ((k0 + 8) ^ sw)];
                unsigned a5 = As[(r + 8) * 32 + ((k0 + 8) ^ sw)];
                unsigned a6 = As[r * 32 + ((k0 + 12) ^ sw)];
                unsigned a7 = As[(r + 8) * 32 + ((k0 + 12) ^ sw)];
#pragma unroll
                for (int nt = 0; nt < 8; nt++) {
                    mma8(acc[mt][nt], a0, a1, a2, a3, bf[nt].x, bf[nt].y);
                    mma8(acc[mt][nt], a4, a5, a6, a7, bf[nt].z, bf[nt].w);
                }
            }
        }
        __syncthreads();
    }

    // ---- epilogue: LSTM cell with peepholes ----
    // cols are gate-interleaved (col = o*4+g). Fragment col pair (2q, 2q+1):
    // q even -> gates (i,f); q odd -> gates (t,o) of the same o. Pair via shfl_xor 1.
    int q = lane & 3, gid = lane >> 2;
    bool evn = !(q & 1);
#pragma unroll
    for (int mt = 0; mt < 2; mt++) {
#pragma unroll
        for (int nt = 0; nt < 8; nt++) {
            float p0 = __shfl_xor_sync(0xffffffffu, acc[mt][nt][0], 1);
            float p1 = __shfl_xor_sync(0xffffffffu, acc[mt][nt][1], 1);
            float p2 = __shfl_xor_sync(0xffffffffu, acc[mt][nt][2], 1);
            float p3 = __shfl_xor_sync(0xffffffffu, acc[mt][nt][3], 1);
            if (evn) {
                int o = warp_n * 16 + nt * 2 + (q >> 1);
                float b0 = bias[4 * o + 0], b1 = bias[4 * o + 1];
                float b2 = bias[4 * o + 2], b3 = bias[4 * o + 3];
                float wpi = wp[o], wpf = wp[64 + o], wpo = wp[128 + o];
#pragma unroll
                for (int rh = 0; rh < 2; rh++) {
                    int n = n0 + warp_m * 32 + mt * 16 + gid + rh * 8;
                    if (n < Nn) {
                        float gi = acc[mt][nt][rh * 2 + 0];
                        float gf = acc[mt][nt][rh * 2 + 1];
                        float gt = rh ? p2 : p0;
                        float go = rh ? p3 : p1;
                        float cv = cl[n * 64 + o];
                        float iv = sigf(gi + b0 + wpi * cv);
                        float fv = sigf(gf + b1 + wpf * cv);
                        float tv = tanhfast(gt + b2);
                        float ct = fv * cv + iv * tv;
                        float ov = sigf(go + b3 + wpo * ct);
                        hout[n * 64 + o] = ov * tanhfast(ct);
                        cout[n * 64 + o] = ct;
                    }
                }
            }
        }
    }
}

// ---------------- final FC ----------------
__global__ void __launch_bounds__(256) k_fc(const float* __restrict__ h1,
                                            const float* __restrict__ fw,
                                            const float* __restrict__ fb,
                                            float* __restrict__ out) {
    int warp = (blockIdx.x * blockDim.x + threadIdx.x) >> 5;
    int lane = threadIdx.x & 31;
    if (warp >= Nn) return;
    float2 v = *(const float2*)(h1 + warp * 64 + lane * 2);
    float2 w = *(const float2*)(fw + lane * 2);
    float s = v.x * w.x + v.y * w.y;
#pragma unroll
    for (int d = 16; d; d >>= 1) s += __shfl_xor_sync(0xffffffffu, s, d);
    if (lane == 0) out[warp] = s + fb[0];
}

// ---------------- launch ----------------
extern "C" void kernel_launch(void* const* d_in, const int* in_sizes, int n_in,
                              void* d_out, int out_size) {
    const float* x   = (const float*)d_in[0];
    const int*   ei  = (const int*)d_in[1];
    const float* ew  = (const float*)d_in[2];
    const float* h   = (const float*)d_in[3];
    const float* c   = (const float*)d_in[4];
    const float* Wx  = (const float*)d_in[5];
    const float* Wch = (const float*)d_in[6];
    const float* bch = (const float*)d_in[7];
    const float* wp  = (const float*)d_in[8];
    const float* bg  = (const float*)d_in[9];
    const float* fw  = (const float*)d_in[10];
    const float* fb  = (const float*)d_in[11];

    float* out  = (float*)d_out;
    float* hout = out + Nn;                 // h_new stacked (L, N, H)
    float* cout = out + Nn + Ll * Nn * Hh;  // c_new stacked (L, N, H)

    const int* row = ei;
    const int* col = ei + Ee;

    const int GATES_SMEM = (128 * 32 + 2048 * 4) * 4;  // 49152 B
    cudaFuncSetAttribute(k_gates, cudaFuncAttributeMaxDynamicSharedMemorySize, GATES_SMEM);

    k_zero<<<(Nn + 255) / 256, 256>>>();
    k_hist<<<(Ee + 255) / 256, 256>>>(row, ew);
    k_dinv<<<(Nn + 255) / 256, 256>>>();
    k_part<<<PBLK, 256>>>();
    k_scanpart<<<1, 256>>>();
    k_csr<<<PBLK, 256>>>();
    k_scatter<<<(Ee + 255) / 256, 256>>>(row, col, ew);
    k_wbig<<<(Ll * 65536 + 255) / 256, 256>>>(Wx, Wch, bch, bg);

    const int spmmBlocks = (Nn * 32 + 255) / 256;  // warp per row
    const int gemmBlocks = (Nn + 127) / 128;

    for (int l = 0; l < Ll; l++) {
        const float* hl  = h + l * Nn * Hh;
        const float* clp = c + l * Nn * Hh;
        const float* inp = (l == 0) ? x : hout;   // layer 1 input = h_new[0]
        float* ho = hout + l * Nn * Hh;
        float* co = cout + l * Nn * Hh;

        k_spmm1<<<spmmBlocks, 256>>>(hl);
        k_spmm2<<<spmmBlocks, 256>>>(hl);
        k_gates<<<gemmBlocks, 512, GATES_SMEM>>>(l, inp, hl, clp, wp + l * 192, ho, co);
    }

    k_fc<<<spmmBlocks, 256>>>(hout + Nn * Hh, fw, fb, out);
}